// round 10
// baseline (speedup 1.0000x reference)
#include <cuda_runtime.h>
#include <cuda_bf16.h>
#include <math.h>

#define B_    2048
#define NIN   1024
#define NH    1024
#define NOUT  512
#define NTOT  3072
#define KCAT  1536
#define NWIN  96
#define T0c   2.0f
#define T1c   1.6374615061559636f   // 2/exp(0.2)

typedef unsigned long long ull;

// ---- device scratch (no runtime allocation allowed) ----
__device__ float g_A[B_ * KCAT];        // [x, s2_init] packed
__device__ float g_WH[KCAT * NH];       // [W1^T ; W2]
__device__ float g_W2T[NH * NOUT];      // W2 transposed
__device__ float g_TH[NTOT * B_];       // thresholds T*logit(u), layout [t][b]
__device__ float g_gapH[B_ * NH];       // init hidden gaps
__device__ float g_gapO[B_ * NOUT];     // init output gaps
__device__ float g_CW[NWIN * 1024];     // cross weights per window [w][i][j]

// ---------------------------------------------------------------------------
// f32x2 helpers
// ---------------------------------------------------------------------------
__device__ __forceinline__ ull pack2f(float lo, float hi) {
    ull r;
    asm("mov.b64 %0, {%1, %2};" : "=l"(r)
        : "r"(__float_as_uint(lo)), "r"(__float_as_uint(hi)));
    return r;
}
__device__ __forceinline__ void fma2(ull& acc, ull a, ull b) {
    asm("fma.rn.f32x2 %0, %1, %2, %0;" : "+l"(acc) : "l"(a), "l"(b));
}

// ---------------------------------------------------------------------------
// Fused prep: segmented grid.
//   [0,3072) pack_A | [3072,4096) W1^T | [4096,4608) W2 copy |
//   [4608,5120) W2^T | [5120,29696) thresholds | [29696,30080) cross weights
// ---------------------------------------------------------------------------
__global__ void __launch_bounds__(256) prep_k(
    const float* __restrict__ x, const float* __restrict__ s2i,
    const float* __restrict__ W1, const float* __restrict__ W2,
    const float* __restrict__ u, const int* __restrict__ ids)
{
    __shared__ float tile[32][33];
    int q = blockIdx.x, tid = threadIdx.x;

    if (q < 3072) {                                   // pack_A
        int idx = q * 256 + tid;
        int b = idx / 384, c = idx % 384;
        float4 v = (c < 256) ? ((const float4*)x)[(size_t)b * 256 + c]
                             : ((const float4*)s2i)[(size_t)b * 128 + (c - 256)];
        ((float4*)g_A)[idx] = v;
    } else if (q < 4096) {                            // transpose W1
        int r = q - 3072;
        int c0 = (r & 31) * 32, r0 = (r >> 5) * 32;
        int tx = tid & 31, ty = tid >> 5;
#pragma unroll
        for (int j = 0; j < 32; j += 8)
            tile[ty + j][tx] = W1[(size_t)(r0 + ty + j) * 1024 + c0 + tx];
        __syncthreads();
#pragma unroll
        for (int j = 0; j < 32; j += 8)
            g_WH[(size_t)(c0 + ty + j) * 1024 + r0 + tx] = tile[tx][ty + j];
    } else if (q < 4608) {                            // copy W2
        int idx = (q - 4096) * 256 + tid;
        ((float4*)(g_WH + 1024 * 1024))[idx] = ((const float4*)W2)[idx];
    } else if (q < 5120) {                            // transpose W2
        int r = q - 4608;
        int c0 = (r & 31) * 32, r0 = (r >> 5) * 32;
        int tx = tid & 31, ty = tid >> 5;
#pragma unroll
        for (int j = 0; j < 32; j += 8)
            tile[ty + j][tx] = W2[(size_t)(r0 + ty + j) * 1024 + c0 + tx];
        __syncthreads();
#pragma unroll
        for (int j = 0; j < 32; j += 8)
            g_W2T[(size_t)(c0 + ty + j) * 512 + r0 + tx] = tile[tx][ty + j];
    } else if (q < 29696) {                           // thresholds
        int idx = (q - 5120) * 256 + tid;
        float T = (idx < 1536 * 2048) ? T0c : T1c;
        float uu = u[idx];
        g_TH[idx] = T * (logf(uu) - log1pf(-uu));
    } else {                                          // cross weights
        int idx = (q - 29696) * 256 + tid;            // 0..98303
        int w = idx >> 10, rest = idx & 1023;
        int i = rest >> 5, j = rest & 31;
        float val = 0.f;
        if (i < j) {
            int a = ids[w * 32 + i], b = ids[w * 32 + j];
            if ((a < NH) != (b < NH)) {
                int o = (a < NH) ? (b - NH) : (a - NH);
                int n = (a < NH) ? a : b;
                val = W2[(size_t)o * NH + n];
            }
        }
        g_CW[idx] = val;
    }
}

// ---------------------------------------------------------------------------
// FP32 GEMM: 128x64 tile, 256 threads, 8x4 microtile, 2 CTAs/SM. (unchanged)
// ---------------------------------------------------------------------------
__global__ void __launch_bounds__(256, 2) gemm_bias_k(
    const float* __restrict__ A, const float* __restrict__ Bm,
    const float* __restrict__ bias, float* __restrict__ C,
    int M, int N, int K)
{
    __shared__ float As[16][132];
    __shared__ float Bs[16][72];
    int t  = threadIdx.x;
    int tx = t & 15, ty = t >> 4;
    int m0 = blockIdx.y * 128, n0 = blockIdx.x * 64;

    int ar = t >> 2;
    int ak = (t & 3) * 4;
    int bk = t >> 4;
    int bc = (t & 15) * 4;

    ull acc[8][2];
#pragma unroll
    for (int i = 0; i < 8; i++) { acc[i][0] = 0ull; acc[i][1] = 0ull; }

    for (int k0 = 0; k0 < K; k0 += 16) {
        float4 a0 = *(const float4*)&A[(size_t)(m0 + ar) * K + k0 + ak];
        float4 a1 = *(const float4*)&A[(size_t)(m0 + ar + 64) * K + k0 + ak];
        float4 b0 = *(const float4*)&Bm[(size_t)(k0 + bk) * N + n0 + bc];
        As[ak + 0][ar] = a0.x; As[ak + 1][ar] = a0.y;
        As[ak + 2][ar] = a0.z; As[ak + 3][ar] = a0.w;
        As[ak + 0][ar + 64] = a1.x; As[ak + 1][ar + 64] = a1.y;
        As[ak + 2][ar + 64] = a1.z; As[ak + 3][ar + 64] = a1.w;
        *(float4*)&Bs[bk][bc] = b0;
        __syncthreads();
#pragma unroll
        for (int k = 0; k < 16; ++k) {
            float4 av0 = *(const float4*)&As[k][ty * 8];
            float4 av1 = *(const float4*)&As[k][ty * 8 + 4];
            const ull* bpp = (const ull*)&Bs[k][tx * 4];
            ull bp0 = bpp[0], bp1 = bpp[1];
            float a[8] = { av0.x, av0.y, av0.z, av0.w,
                           av1.x, av1.y, av1.z, av1.w };
#pragma unroll
            for (int i = 0; i < 8; i++) {
                ull a2 = pack2f(a[i], a[i]);
                fma2(acc[i][0], bp0, a2);
                fma2(acc[i][1], bp1, a2);
            }
        }
        __syncthreads();
    }

    float4 bv = *(const float4*)&bias[n0 + tx * 4];
    float bb[4] = { bv.x, bv.y, bv.z, bv.w };
#pragma unroll
    for (int i = 0; i < 8; i++) {
        float4 o;
        o.x = __uint_as_float((unsigned)acc[i][0]) + bb[0];
        o.y = __uint_as_float((unsigned)(acc[i][0] >> 32)) + bb[1];
        o.z = __uint_as_float((unsigned)acc[i][1]) + bb[2];
        o.w = __uint_as_float((unsigned)(acc[i][1] >> 32)) + bb[3];
        *(float4*)&C[(size_t)(m0 + ty * 8 + i) * N + n0 + tx * 4] = o;
    }
}

// ---------------------------------------------------------------------------
// Gibbs v5: window-batched. 256 blocks x 256 threads, 8 chains/block, 2/SM.
// 96 windows of 32 updates; 8 sequencer threads do triangular decisions;
// all threads apply rank-r corrections to register gaps.
// smem floats:
//  s_s[12288] | cw_s[1024] | bg_s[256] | d_s[256] | ids(ushort)[3072]->1536f |
//  upos(ushort)[3072]->1536f | lst(uchar)[3072]->768f | hw[96] | cnt[96]
// ---------------------------------------------------------------------------
#define SM_S    0
#define SM_CW   12288
#define SM_BG   13312
#define SM_D    13568
#define SM_IDS  13824
#define SM_UPOS 15360
#define SM_LST  16896
#define SM_HW   17664
#define SM_CNT  17760
#define SMEM_FLOATS 17856
#define SMEM_BYTES  (SMEM_FLOATS * 4)

__global__ void __launch_bounds__(256, 2) gibbs_k(
    const float* __restrict__ x, const float* __restrict__ s1i,
    const float* __restrict__ s2i, const float* __restrict__ W2,
    const int* __restrict__ ids, float* __restrict__ out)
{
    extern __shared__ float sm[];
    float* s_s  = sm + SM_S;
    float* cw_s = sm + SM_CW;
    float* bg_s = sm + SM_BG;
    float* d_s  = sm + SM_D;
    unsigned short* ids_s = (unsigned short*)(sm + SM_IDS);
    unsigned short* upos  = (unsigned short*)(sm + SM_UPOS);
    unsigned char*  lst_s = (unsigned char*)(sm + SM_LST);
    unsigned* hw_s  = (unsigned*)(sm + SM_HW);
    unsigned* cnt_s = (unsigned*)(sm + SM_CNT);

    int tid = threadIdx.x, lane = tid & 31, wid = tid >> 5;
    int c0  = blockIdx.x * 8;

    for (int i = tid; i < NTOT; i += 256) ids_s[i] = (unsigned short)ids[i];
    __syncthreads();

    // hword per window (bit j = 1 iff unit is hidden)
    for (int g = wid; g < NWIN; g += 8) {
        int v = ids_s[g * 32 + lane];
        unsigned m = __ballot_sync(0xffffffffu, v < NH);
        if (lane == 0) hw_s[g] = m;
    }
    // per-window ordered lists: H positions first, then O positions
    for (int w = tid; w < NWIN; w += 256) {
        int hc = 0;
        for (int j = 0; j < 32; j++)
            if (ids_s[w * 32 + j] < NH) lst_s[w * 32 + hc++] = (unsigned char)j;
        cnt_s[w] = hc;
        int oc = hc;
        for (int j = 0; j < 32; j++)
            if (ids_s[w * 32 + j] >= NH) lst_s[w * 32 + oc++] = (unsigned char)j;
    }
    // position of each unit per sweep
    for (int p = tid; p < NTOT; p += 256) {
        int n = ids_s[p];
        upos[n + (p >= 1536 ? 1536 : 0)] = (unsigned short)p;
    }
    // state floats s_s[n*8+c]
    for (int i = tid; i < 1536; i += 256) {
#pragma unroll
        for (int c = 0; c < 8; c++) {
            float v = (i < NH) ? s1i[(size_t)(c0 + c) * NH + i]
                               : s2i[(size_t)(c0 + c) * NOUT + (i - NH)];
            s_s[i * 8 + c] = (v > 0.5f) ? 1.f : 0.f;
        }
    }

    // register gaps
    ull rH[4][4], rO[2][4];
#pragma unroll
    for (int u = 0; u < 4; u++)
#pragma unroll
        for (int p = 0; p < 4; p++)
            rH[u][p] = pack2f(g_gapH[(size_t)(c0 + 2 * p) * NH + 4 * tid + u],
                              g_gapH[(size_t)(c0 + 2 * p + 1) * NH + 4 * tid + u]);
#pragma unroll
    for (int v = 0; v < 2; v++)
#pragma unroll
        for (int p = 0; p < 4; p++)
            rO[v][p] = pack2f(g_gapO[(size_t)(c0 + 2 * p) * NOUT + 2 * tid + v],
                              g_gapO[(size_t)(c0 + 2 * p + 1) * NOUT + 2 * tid + v]);
    __syncthreads();

    // my 12 owned positions (4 H units x2 sweeps, 2 O units x2 sweeps)
    int mypos[12];
#pragma unroll
    for (int k = 0; k < 4; k++) {
        mypos[k]     = upos[4 * tid + k];
        mypos[k + 4] = upos[4 * tid + k + 1536];
    }
#pragma unroll
    for (int k = 0; k < 2; k++) {
        mypos[8 + k]  = upos[NH + 2 * tid + k];
        mypos[10 + k] = upos[NH + 2 * tid + k + 1536];
    }

    // stage window 0 base gaps
#define STAGE_WIN(NBASE)                                                     \
    {                                                                        \
        _Pragma("unroll")                                                    \
        for (int k = 0; k < 12; k++) {                                       \
            int pos = mypos[k];                                              \
            if (pos >= (NBASE) && pos < (NBASE) + 32) {                      \
                int j = pos - (NBASE);                                       \
                ull* bq = (ull*)bg_s + j * 4;                                \
                if (k < 8) {                                                 \
                    int u = k & 3;                                           \
                    _Pragma("unroll")                                        \
                    for (int p = 0; p < 4; p++) bq[p] = rH[u][p];            \
                } else {                                                     \
                    int v = k & 1;                                           \
                    _Pragma("unroll")                                        \
                    for (int p = 0; p < 4; p++) bq[p] = rO[v][p];            \
                }                                                            \
            }                                                                \
        }                                                                    \
    }
    STAGE_WIN(0)
    // load cw(0), prefetch th(0)
    ((float4*)cw_s)[tid] = ((const float4*)g_CW)[tid];
    if (tid < 32)
        asm volatile("prefetch.global.L1 [%0];"
                     :: "l"(&g_TH[(size_t)tid * B_ + c0]));
    __syncthreads();

    for (int w = 0; w < NWIN; w++) {
        int base = w * 32;

        // ===== sequencer phase =====
        if (tid < 8) {
            int c = tid;
            unsigned hword = hw_s[w];
            const float* thp = g_TH + (size_t)base * B_ + c0 + c;
            unsigned dP = 0, dM = 0;
#pragma unroll 1
            for (int j = 0; j < 32; j++) {
                int n = ids_s[base + j];
                float g = bg_s[j * 8 + c];
                unsigned below = (j == 0) ? 0u : (0xffffffffu >> (32 - j));
                unsigned cm = (((hword >> j) & 1u) ? ~hword : hword) & below;
                unsigned act = cm & (dP | dM);
                while (act) {
                    int i = __ffs(act) - 1;
                    act &= act - 1;
                    float cv = cw_s[i * 32 + j];
                    g = ((dP >> i) & 1u) ? (g + cv) : (g - cv);
                }
                float th = __ldg(thp + (size_t)j * B_);
                float ov = s_s[n * 8 + c];
                float nv = (g > th) ? 1.f : 0.f;
                float d = nv - ov;
                d_s[j * 8 + c] = d;
                s_s[n * 8 + c] = nv;
                if (d > 0.5f) dP |= 1u << j;
                else if (d < -0.5f) dM |= 1u << j;
            }
        } else {
            // prefetch this window's weight slices (own future addresses)
            for (int k = 0; k < 32; k++) {
                int j = lst_s[w * 32 + k];
                int n = ids_s[base + j];
                const float* wp = (n < NH)
                    ? (g_W2T + (size_t)n * NOUT + 2 * tid)
                    : (W2 + (size_t)(n - NH) * NH + 4 * tid);
                asm volatile("prefetch.global.L1 [%0];" :: "l"(wp));
            }
            // prefetch next window's thresholds
            if (tid < 40 && w + 1 < NWIN)
                asm volatile("prefetch.global.L1 [%0];"
                             :: "l"(&g_TH[(size_t)(base + 32 + tid - 8) * B_ + c0]));
        }
        __syncthreads();

        // ===== apply phase =====
        int hcnt = cnt_s[w];
        for (int k = 0; k < hcnt; k++) {
            int j = lst_s[w * 32 + k];
            int n = ids_s[base + j];
            float2 wv = __ldg((const float2*)(g_W2T + (size_t)n * NOUT + 2 * tid));
            ull w0 = pack2f(wv.x, wv.x);
            ull w1 = pack2f(wv.y, wv.y);
            const ull* dp = (const ull*)(d_s + j * 8);
#pragma unroll
            for (int p = 0; p < 4; p++) {
                ull d = dp[p];
                fma2(rO[0][p], d, w0);
                fma2(rO[1][p], d, w1);
            }
        }
        for (int k = hcnt; k < 32; k++) {
            int j = lst_s[w * 32 + k];
            int o = ids_s[base + j] - NH;
            float4 wv = __ldg((const float4*)(W2 + (size_t)o * NH + 4 * tid));
            ull w0 = pack2f(wv.x, wv.x);
            ull w1 = pack2f(wv.y, wv.y);
            ull w2_ = pack2f(wv.z, wv.z);
            ull w3 = pack2f(wv.w, wv.w);
            const ull* dp = (const ull*)(d_s + j * 8);
#pragma unroll
            for (int p = 0; p < 4; p++) {
                ull d = dp[p];
                fma2(rH[0][p], d, w0);
                fma2(rH[1][p], d, w1);
                fma2(rH[2][p], d, w2_);
                fma2(rH[3][p], d, w3);
            }
        }
        // stage next window's base gaps + cross weights
        if (w + 1 < NWIN) {
            int nb = base + 32;
            STAGE_WIN(nb)
            ((float4*)cw_s)[tid] =
                ((const float4*)(g_CW + (size_t)(w + 1) * 1024))[tid];
        }
        __syncthreads();
    }

    // ===== epilogue =====
#pragma unroll
    for (int c = 0; c < 8; c++) {
        int b = c0 + c;
        size_t rb4 = (size_t)b * 640;
        ((float4*)out)[rb4 + tid] = ((const float4*)x)[(size_t)b * 256 + tid];
        float4 v1;
        v1.x = s_s[(4 * tid + 0) * 8 + c];
        v1.y = s_s[(4 * tid + 1) * 8 + c];
        v1.z = s_s[(4 * tid + 2) * 8 + c];
        v1.w = s_s[(4 * tid + 3) * 8 + c];
        ((float4*)out)[rb4 + 256 + tid] = v1;
        if (tid < 128) {
            float4 v2;
            v2.x = s_s[(1024 + 4 * tid + 0) * 8 + c];
            v2.y = s_s[(1024 + 4 * tid + 1) * 8 + c];
            v2.z = s_s[(1024 + 4 * tid + 2) * 8 + c];
            v2.w = s_s[(1024 + 4 * tid + 3) * 8 + c];
            ((float4*)out)[rb4 + 512 + tid] = v2;
        }
    }
}

// ---------------------------------------------------------------------------
extern "C" void kernel_launch(void* const* d_in, const int* in_sizes, int n_in,
                              void* d_out, int out_size)
{
    const float* x   = (const float*)d_in[0];
    const float* s1i = (const float*)d_in[1];
    const float* s2i = (const float*)d_in[2];
    const float* W1  = (const float*)d_in[3];
    const float* b1  = (const float*)d_in[4];
    const float* W2  = (const float*)d_in[5];
    const float* b2  = (const float*)d_in[6];
    const float* u   = (const float*)d_in[7];
    const int*   ids = (const int*)d_in[8];
    float* out = (float*)d_out;

    float *pA, *pWH, *pW2T, *pGH, *pGO;
    cudaGetSymbolAddress((void**)&pA,   g_A);
    cudaGetSymbolAddress((void**)&pWH,  g_WH);
    cudaGetSymbolAddress((void**)&pW2T, g_W2T);
    cudaGetSymbolAddress((void**)&pGH,  g_gapH);
    cudaGetSymbolAddress((void**)&pGO,  g_gapO);

    prep_k     <<<30080, 256>>>(x, s2i, W1, W2, u, ids);
    gemm_bias_k<<<dim3(16, 16), 256>>>(pA,  pWH,  b1, pGH, 2048, 1024, 1536);
    gemm_bias_k<<<dim3(8, 16),  256>>>(s1i, pW2T, b2, pGO, 2048, 512, 1024);

    cudaFuncSetAttribute(gibbs_k, cudaFuncAttributeMaxDynamicSharedMemorySize,
                         SMEM_BYTES);
    gibbs_k<<<256, 256, SMEM_BYTES>>>(x, s1i, s2i, W2, ids, out);
}

// round 11
// speedup vs baseline: 1.0052x; 1.0052x over previous
#include <cuda_runtime.h>
#include <cuda_bf16.h>
#include <math.h>

#define B_    2048
#define NIN   1024
#define NH    1024
#define NOUT  512
#define NTOT  3072
#define KCAT  1536
#define NWIN  96
#define T0c   2.0f
#define T1c   1.6374615061559636f   // 2/exp(0.2)

typedef unsigned long long ull;

// ---- device scratch (no runtime allocation allowed) ----
__device__ float g_A[B_ * KCAT];        // [x, s2_init] packed
__device__ float g_WH[KCAT * NH];       // [W1^T ; W2]
__device__ float g_W2T[NH * NOUT];      // W2 transposed
__device__ float g_TH[NTOT * B_];       // thresholds T*logit(u), layout [t][b]
__device__ float g_gapH[B_ * NH];       // init hidden gaps
__device__ float g_gapO[B_ * NOUT];     // init output gaps
__device__ float g_CW[NWIN * 1024];     // cross weights per window [w][i][j]

// ---------------------------------------------------------------------------
// f32x2 helpers
// ---------------------------------------------------------------------------
__device__ __forceinline__ ull pack2f(float lo, float hi) {
    ull r;
    asm("mov.b64 %0, {%1, %2};" : "=l"(r)
        : "r"(__float_as_uint(lo)), "r"(__float_as_uint(hi)));
    return r;
}
__device__ __forceinline__ void fma2(ull& acc, ull a, ull b) {
    asm("fma.rn.f32x2 %0, %1, %2, %0;" : "+l"(acc) : "l"(a), "l"(b));
}

// ---------------------------------------------------------------------------
// Fused prep: segmented grid.
//   [0,3072) pack_A | [3072,4096) W1^T | [4096,4608) W2 copy |
//   [4608,5120) W2^T | [5120,29696) thresholds | [29696,30080) cross weights
// ---------------------------------------------------------------------------
__global__ void __launch_bounds__(256) prep_k(
    const float* __restrict__ x, const float* __restrict__ s2i,
    const float* __restrict__ W1, const float* __restrict__ W2,
    const float* __restrict__ u, const int* __restrict__ ids)
{
    __shared__ float tile[32][33];
    int q = blockIdx.x, tid = threadIdx.x;

    if (q < 3072) {                                   // pack_A
        int idx = q * 256 + tid;
        int b = idx / 384, c = idx % 384;
        float4 v = (c < 256) ? ((const float4*)x)[(size_t)b * 256 + c]
                             : ((const float4*)s2i)[(size_t)b * 128 + (c - 256)];
        ((float4*)g_A)[idx] = v;
    } else if (q < 4096) {                            // transpose W1
        int r = q - 3072;
        int c0 = (r & 31) * 32, r0 = (r >> 5) * 32;
        int tx = tid & 31, ty = tid >> 5;
#pragma unroll
        for (int j = 0; j < 32; j += 8)
            tile[ty + j][tx] = W1[(size_t)(r0 + ty + j) * 1024 + c0 + tx];
        __syncthreads();
#pragma unroll
        for (int j = 0; j < 32; j += 8)
            g_WH[(size_t)(c0 + ty + j) * 1024 + r0 + tx] = tile[tx][ty + j];
    } else if (q < 4608) {                            // copy W2
        int idx = (q - 4096) * 256 + tid;
        ((float4*)(g_WH + 1024 * 1024))[idx] = ((const float4*)W2)[idx];
    } else if (q < 5120) {                            // transpose W2
        int r = q - 4608;
        int c0 = (r & 31) * 32, r0 = (r >> 5) * 32;
        int tx = tid & 31, ty = tid >> 5;
#pragma unroll
        for (int j = 0; j < 32; j += 8)
            tile[ty + j][tx] = W2[(size_t)(r0 + ty + j) * 1024 + c0 + tx];
        __syncthreads();
#pragma unroll
        for (int j = 0; j < 32; j += 8)
            g_W2T[(size_t)(c0 + ty + j) * 512 + r0 + tx] = tile[tx][ty + j];
    } else if (q < 29696) {                           // thresholds
        int idx = (q - 5120) * 256 + tid;
        float T = (idx < 1536 * 2048) ? T0c : T1c;
        float uu = u[idx];
        g_TH[idx] = T * (logf(uu) - log1pf(-uu));
    } else {                                          // cross weights
        int idx = (q - 29696) * 256 + tid;            // 0..98303
        int w = idx >> 10, rest = idx & 1023;
        int i = rest >> 5, j = rest & 31;
        float val = 0.f;
        if (i < j) {
            int a = ids[w * 32 + i], b = ids[w * 32 + j];
            if ((a < NH) != (b < NH)) {
                int o = (a < NH) ? (b - NH) : (a - NH);
                int n = (a < NH) ? a : b;
                val = W2[(size_t)o * NH + n];
            }
        }
        g_CW[idx] = val;
    }
}

// ---------------------------------------------------------------------------
// FP32 GEMM: 128x64 tile, 256 threads, 8x4 microtile, 2 CTAs/SM. (unchanged)
// ---------------------------------------------------------------------------
__global__ void __launch_bounds__(256, 2) gemm_bias_k(
    const float* __restrict__ A, const float* __restrict__ Bm,
    const float* __restrict__ bias, float* __restrict__ C,
    int M, int N, int K)
{
    __shared__ float As[16][132];
    __shared__ float Bs[16][72];
    int t  = threadIdx.x;
    int tx = t & 15, ty = t >> 4;
    int m0 = blockIdx.y * 128, n0 = blockIdx.x * 64;

    int ar = t >> 2;
    int ak = (t & 3) * 4;
    int bk = t >> 4;
    int bc = (t & 15) * 4;

    ull acc[8][2];
#pragma unroll
    for (int i = 0; i < 8; i++) { acc[i][0] = 0ull; acc[i][1] = 0ull; }

    for (int k0 = 0; k0 < K; k0 += 16) {
        float4 a0 = *(const float4*)&A[(size_t)(m0 + ar) * K + k0 + ak];
        float4 a1 = *(const float4*)&A[(size_t)(m0 + ar + 64) * K + k0 + ak];
        float4 b0 = *(const float4*)&Bm[(size_t)(k0 + bk) * N + n0 + bc];
        As[ak + 0][ar] = a0.x; As[ak + 1][ar] = a0.y;
        As[ak + 2][ar] = a0.z; As[ak + 3][ar] = a0.w;
        As[ak + 0][ar + 64] = a1.x; As[ak + 1][ar + 64] = a1.y;
        As[ak + 2][ar + 64] = a1.z; As[ak + 3][ar + 64] = a1.w;
        *(float4*)&Bs[bk][bc] = b0;
        __syncthreads();
#pragma unroll
        for (int k = 0; k < 16; ++k) {
            float4 av0 = *(const float4*)&As[k][ty * 8];
            float4 av1 = *(const float4*)&As[k][ty * 8 + 4];
            const ull* bpp = (const ull*)&Bs[k][tx * 4];
            ull bp0 = bpp[0], bp1 = bpp[1];
            float a[8] = { av0.x, av0.y, av0.z, av0.w,
                           av1.x, av1.y, av1.z, av1.w };
#pragma unroll
            for (int i = 0; i < 8; i++) {
                ull a2 = pack2f(a[i], a[i]);
                fma2(acc[i][0], bp0, a2);
                fma2(acc[i][1], bp1, a2);
            }
        }
        __syncthreads();
    }

    float4 bv = *(const float4*)&bias[n0 + tx * 4];
    float bb[4] = { bv.x, bv.y, bv.z, bv.w };
#pragma unroll
    for (int i = 0; i < 8; i++) {
        float4 o;
        o.x = __uint_as_float((unsigned)acc[i][0]) + bb[0];
        o.y = __uint_as_float((unsigned)(acc[i][0] >> 32)) + bb[1];
        o.z = __uint_as_float((unsigned)acc[i][1]) + bb[2];
        o.w = __uint_as_float((unsigned)(acc[i][1] >> 32)) + bb[3];
        *(float4*)&C[(size_t)(m0 + ty * 8 + i) * N + n0 + tx * 4] = o;
    }
}

// ---------------------------------------------------------------------------
// Gibbs v5: window-batched. 256 blocks x 256 threads, 8 chains/block, 2/SM.
// 96 windows of 32 updates; 8 sequencer threads do triangular decisions;
// all threads apply rank-r corrections to register gaps.
// smem floats:
//  s_s[12288] | cw_s[1024] | bg_s[256] | d_s[256] | ids(ushort)[3072]->1536f |
//  upos(ushort)[3072]->1536f | lst(uchar)[3072]->768f | hw[96] | cnt[96]
// ---------------------------------------------------------------------------
#define SM_S    0
#define SM_CW   12288
#define SM_BG   13312
#define SM_D    13568
#define SM_IDS  13824
#define SM_UPOS 15360
#define SM_LST  16896
#define SM_HW   17664
#define SM_CNT  17760
#define SMEM_FLOATS 17856
#define SMEM_BYTES  (SMEM_FLOATS * 4)

__global__ void __launch_bounds__(256, 2) gibbs_k(
    const float* __restrict__ x, const float* __restrict__ s1i,
    const float* __restrict__ s2i, const float* __restrict__ W2,
    const int* __restrict__ ids, float* __restrict__ out)
{
    extern __shared__ float sm[];
    float* s_s  = sm + SM_S;
    float* cw_s = sm + SM_CW;
    float* bg_s = sm + SM_BG;
    float* d_s  = sm + SM_D;
    unsigned short* ids_s = (unsigned short*)(sm + SM_IDS);
    unsigned short* upos  = (unsigned short*)(sm + SM_UPOS);
    unsigned char*  lst_s = (unsigned char*)(sm + SM_LST);
    unsigned* hw_s  = (unsigned*)(sm + SM_HW);
    unsigned* cnt_s = (unsigned*)(sm + SM_CNT);

    int tid = threadIdx.x, lane = tid & 31, wid = tid >> 5;
    int c0  = blockIdx.x * 8;

    for (int i = tid; i < NTOT; i += 256) ids_s[i] = (unsigned short)ids[i];
    __syncthreads();

    // hword per window (bit j = 1 iff unit is hidden)
    for (int g = wid; g < NWIN; g += 8) {
        int v = ids_s[g * 32 + lane];
        unsigned m = __ballot_sync(0xffffffffu, v < NH);
        if (lane == 0) hw_s[g] = m;
    }
    // per-window ordered lists: H positions first, then O positions
    for (int w = tid; w < NWIN; w += 256) {
        int hc = 0;
        for (int j = 0; j < 32; j++)
            if (ids_s[w * 32 + j] < NH) lst_s[w * 32 + hc++] = (unsigned char)j;
        cnt_s[w] = hc;
        int oc = hc;
        for (int j = 0; j < 32; j++)
            if (ids_s[w * 32 + j] >= NH) lst_s[w * 32 + oc++] = (unsigned char)j;
    }
    // position of each unit per sweep
    for (int p = tid; p < NTOT; p += 256) {
        int n = ids_s[p];
        upos[n + (p >= 1536 ? 1536 : 0)] = (unsigned short)p;
    }
    // state floats s_s[n*8+c]
    for (int i = tid; i < 1536; i += 256) {
#pragma unroll
        for (int c = 0; c < 8; c++) {
            float v = (i < NH) ? s1i[(size_t)(c0 + c) * NH + i]
                               : s2i[(size_t)(c0 + c) * NOUT + (i - NH)];
            s_s[i * 8 + c] = (v > 0.5f) ? 1.f : 0.f;
        }
    }

    // register gaps
    ull rH[4][4], rO[2][4];
#pragma unroll
    for (int u = 0; u < 4; u++)
#pragma unroll
        for (int p = 0; p < 4; p++)
            rH[u][p] = pack2f(g_gapH[(size_t)(c0 + 2 * p) * NH + 4 * tid + u],
                              g_gapH[(size_t)(c0 + 2 * p + 1) * NH + 4 * tid + u]);
#pragma unroll
    for (int v = 0; v < 2; v++)
#pragma unroll
        for (int p = 0; p < 4; p++)
            rO[v][p] = pack2f(g_gapO[(size_t)(c0 + 2 * p) * NOUT + 2 * tid + v],
                              g_gapO[(size_t)(c0 + 2 * p + 1) * NOUT + 2 * tid + v]);
    __syncthreads();

    // my 12 owned positions (4 H units x2 sweeps, 2 O units x2 sweeps)
    int mypos[12];
#pragma unroll
    for (int k = 0; k < 4; k++) {
        mypos[k]     = upos[4 * tid + k];
        mypos[k + 4] = upos[4 * tid + k + 1536];
    }
#pragma unroll
    for (int k = 0; k < 2; k++) {
        mypos[8 + k]  = upos[NH + 2 * tid + k];
        mypos[10 + k] = upos[NH + 2 * tid + k + 1536];
    }

    // stage window 0 base gaps
#define STAGE_WIN(NBASE)                                                     \
    {                                                                        \
        _Pragma("unroll")                                                    \
        for (int k = 0; k < 12; k++) {                                       \
            int pos = mypos[k];                                              \
            if (pos >= (NBASE) && pos < (NBASE) + 32) {                      \
                int j = pos - (NBASE);                                       \
                ull* bq = (ull*)bg_s + j * 4;                                \
                if (k < 8) {                                                 \
                    int u = k & 3;                                           \
                    _Pragma("unroll")                                        \
                    for (int p = 0; p < 4; p++) bq[p] = rH[u][p];            \
                } else {                                                     \
                    int v = k & 1;                                           \
                    _Pragma("unroll")                                        \
                    for (int p = 0; p < 4; p++) bq[p] = rO[v][p];            \
                }                                                            \
            }                                                                \
        }                                                                    \
    }
    STAGE_WIN(0)
    // load cw(0), prefetch th(0)
    ((float4*)cw_s)[tid] = ((const float4*)g_CW)[tid];
    if (tid < 32)
        asm volatile("prefetch.global.L1 [%0];"
                     :: "l"(&g_TH[(size_t)tid * B_ + c0]));
    __syncthreads();

    for (int w = 0; w < NWIN; w++) {
        int base = w * 32;

        // ===== sequencer phase =====
        if (tid < 8) {
            int c = tid;
            unsigned hword = hw_s[w];
            const float* thp = g_TH + (size_t)base * B_ + c0 + c;
            unsigned dP = 0, dM = 0;
#pragma unroll 1
            for (int j = 0; j < 32; j++) {
                int n = ids_s[base + j];
                float g = bg_s[j * 8 + c];
                unsigned below = (j == 0) ? 0u : (0xffffffffu >> (32 - j));
                unsigned cm = (((hword >> j) & 1u) ? ~hword : hword) & below;
                unsigned act = cm & (dP | dM);
                while (act) {
                    int i = __ffs(act) - 1;
                    act &= act - 1;
                    float cv = cw_s[i * 32 + j];
                    g = ((dP >> i) & 1u) ? (g + cv) : (g - cv);
                }
                float th = __ldg(thp + (size_t)j * B_);
                float ov = s_s[n * 8 + c];
                float nv = (g > th) ? 1.f : 0.f;
                float d = nv - ov;
                d_s[j * 8 + c] = d;
                s_s[n * 8 + c] = nv;
                if (d > 0.5f) dP |= 1u << j;
                else if (d < -0.5f) dM |= 1u << j;
            }
        } else {
            // prefetch this window's weight slices (own future addresses)
            for (int k = 0; k < 32; k++) {
                int j = lst_s[w * 32 + k];
                int n = ids_s[base + j];
                const float* wp = (n < NH)
                    ? (g_W2T + (size_t)n * NOUT + 2 * tid)
                    : (W2 + (size_t)(n - NH) * NH + 4 * tid);
                asm volatile("prefetch.global.L1 [%0];" :: "l"(wp));
            }
            // prefetch next window's thresholds
            if (tid < 40 && w + 1 < NWIN)
                asm volatile("prefetch.global.L1 [%0];"
                             :: "l"(&g_TH[(size_t)(base + 32 + tid - 8) * B_ + c0]));
        }
        __syncthreads();

        // ===== apply phase =====
        int hcnt = cnt_s[w];
        for (int k = 0; k < hcnt; k++) {
            int j = lst_s[w * 32 + k];
            int n = ids_s[base + j];
            float2 wv = __ldg((const float2*)(g_W2T + (size_t)n * NOUT + 2 * tid));
            ull w0 = pack2f(wv.x, wv.x);
            ull w1 = pack2f(wv.y, wv.y);
            const ull* dp = (const ull*)(d_s + j * 8);
#pragma unroll
            for (int p = 0; p < 4; p++) {
                ull d = dp[p];
                fma2(rO[0][p], d, w0);
                fma2(rO[1][p], d, w1);
            }
        }
        for (int k = hcnt; k < 32; k++) {
            int j = lst_s[w * 32 + k];
            int o = ids_s[base + j] - NH;
            float4 wv = __ldg((const float4*)(W2 + (size_t)o * NH + 4 * tid));
            ull w0 = pack2f(wv.x, wv.x);
            ull w1 = pack2f(wv.y, wv.y);
            ull w2_ = pack2f(wv.z, wv.z);
            ull w3 = pack2f(wv.w, wv.w);
            const ull* dp = (const ull*)(d_s + j * 8);
#pragma unroll
            for (int p = 0; p < 4; p++) {
                ull d = dp[p];
                fma2(rH[0][p], d, w0);
                fma2(rH[1][p], d, w1);
                fma2(rH[2][p], d, w2_);
                fma2(rH[3][p], d, w3);
            }
        }
        // stage next window's base gaps + cross weights
        if (w + 1 < NWIN) {
            int nb = base + 32;
            STAGE_WIN(nb)
            ((float4*)cw_s)[tid] =
                ((const float4*)(g_CW + (size_t)(w + 1) * 1024))[tid];
        }
        __syncthreads();
    }

    // ===== epilogue =====
#pragma unroll
    for (int c = 0; c < 8; c++) {
        int b = c0 + c;
        size_t rb4 = (size_t)b * 640;
        ((float4*)out)[rb4 + tid] = ((const float4*)x)[(size_t)b * 256 + tid];
        float4 v1;
        v1.x = s_s[(4 * tid + 0) * 8 + c];
        v1.y = s_s[(4 * tid + 1) * 8 + c];
        v1.z = s_s[(4 * tid + 2) * 8 + c];
        v1.w = s_s[(4 * tid + 3) * 8 + c];
        ((float4*)out)[rb4 + 256 + tid] = v1;
        if (tid < 128) {
            float4 v2;
            v2.x = s_s[(1024 + 4 * tid + 0) * 8 + c];
            v2.y = s_s[(1024 + 4 * tid + 1) * 8 + c];
            v2.z = s_s[(1024 + 4 * tid + 2) * 8 + c];
            v2.w = s_s[(1024 + 4 * tid + 3) * 8 + c];
            ((float4*)out)[rb4 + 512 + tid] = v2;
        }
    }
}

// ---------------------------------------------------------------------------
extern "C" void kernel_launch(void* const* d_in, const int* in_sizes, int n_in,
                              void* d_out, int out_size)
{
    const float* x   = (const float*)d_in[0];
    const float* s1i = (const float*)d_in[1];
    const float* s2i = (const float*)d_in[2];
    const float* W1  = (const float*)d_in[3];
    const float* b1  = (const float*)d_in[4];
    const float* W2  = (const float*)d_in[5];
    const float* b2  = (const float*)d_in[6];
    const float* u   = (const float*)d_in[7];
    const int*   ids = (const int*)d_in[8];
    float* out = (float*)d_out;

    float *pA, *pWH, *pW2T, *pGH, *pGO;
    cudaGetSymbolAddress((void**)&pA,   g_A);
    cudaGetSymbolAddress((void**)&pWH,  g_WH);
    cudaGetSymbolAddress((void**)&pW2T, g_W2T);
    cudaGetSymbolAddress((void**)&pGH,  g_gapH);
    cudaGetSymbolAddress((void**)&pGO,  g_gapO);

    prep_k     <<<30080, 256>>>(x, s2i, W1, W2, u, ids);
    gemm_bias_k<<<dim3(16, 16), 256>>>(pA,  pWH,  b1, pGH, 2048, 1024, 1536);
    gemm_bias_k<<<dim3(8, 16),  256>>>(s1i, pW2T, b2, pGO, 2048, 512, 1024);

    cudaFuncSetAttribute(gibbs_k, cudaFuncAttributeMaxDynamicSharedMemorySize,
                         SMEM_BYTES);
    gibbs_k<<<256, 256, SMEM_BYTES>>>(x, s1i, s2i, W2, ids, out);
}

// round 12
// speedup vs baseline: 1.0073x; 1.0021x over previous
#include <cuda_runtime.h>
#include <cuda_bf16.h>
#include <math.h>

#define B_    2048
#define NIN   1024
#define NH    1024
#define NOUT  512
#define NTOT  3072
#define KCAT  1536
#define NWIN  96
#define T0c   2.0f
#define T1c   1.6374615061559636f   // 2/exp(0.2)

typedef unsigned long long ull;

// ---- device scratch (no runtime allocation allowed) ----
__device__ float g_A[B_ * KCAT];        // [x, s2_init] packed
__device__ float g_WH[KCAT * NH];       // [W1^T ; W2]
__device__ float g_W2T[NH * NOUT];      // W2 transposed
__device__ float g_TH[NTOT * B_];       // thresholds T*logit(u), layout [t][b]
__device__ float g_gapH[B_ * NH];       // init hidden gaps
__device__ float g_gapO[B_ * NOUT];     // init output gaps
__device__ float g_CW[NWIN * 1024];     // cross weights per window [w][i][j]

// ---------------------------------------------------------------------------
// f32x2 helpers
// ---------------------------------------------------------------------------
__device__ __forceinline__ ull pack2f(float lo, float hi) {
    ull r;
    asm("mov.b64 %0, {%1, %2};" : "=l"(r)
        : "r"(__float_as_uint(lo)), "r"(__float_as_uint(hi)));
    return r;
}
__device__ __forceinline__ void fma2(ull& acc, ull a, ull b) {
    asm("fma.rn.f32x2 %0, %1, %2, %0;" : "+l"(acc) : "l"(a), "l"(b));
}

// ---------------------------------------------------------------------------
// Fused prep: segmented grid.
//   [0,3072) pack_A | [3072,4096) W1^T | [4096,4608) W2 copy |
//   [4608,5120) W2^T | [5120,29696) thresholds | [29696,30080) cross weights
// ---------------------------------------------------------------------------
__global__ void __launch_bounds__(256) prep_k(
    const float* __restrict__ x, const float* __restrict__ s2i,
    const float* __restrict__ W1, const float* __restrict__ W2,
    const float* __restrict__ u, const int* __restrict__ ids)
{
    __shared__ float tile[32][33];
    int q = blockIdx.x, tid = threadIdx.x;

    if (q < 3072) {                                   // pack_A
        int idx = q * 256 + tid;
        int b = idx / 384, c = idx % 384;
        float4 v = (c < 256) ? ((const float4*)x)[(size_t)b * 256 + c]
                             : ((const float4*)s2i)[(size_t)b * 128 + (c - 256)];
        ((float4*)g_A)[idx] = v;
    } else if (q < 4096) {                            // transpose W1
        int r = q - 3072;
        int c0 = (r & 31) * 32, r0 = (r >> 5) * 32;
        int tx = tid & 31, ty = tid >> 5;
#pragma unroll
        for (int j = 0; j < 32; j += 8)
            tile[ty + j][tx] = W1[(size_t)(r0 + ty + j) * 1024 + c0 + tx];
        __syncthreads();
#pragma unroll
        for (int j = 0; j < 32; j += 8)
            g_WH[(size_t)(c0 + ty + j) * 1024 + r0 + tx] = tile[tx][ty + j];
    } else if (q < 4608) {                            // copy W2
        int idx = (q - 4096) * 256 + tid;
        ((float4*)(g_WH + 1024 * 1024))[idx] = ((const float4*)W2)[idx];
    } else if (q < 5120) {                            // transpose W2
        int r = q - 4608;
        int c0 = (r & 31) * 32, r0 = (r >> 5) * 32;
        int tx = tid & 31, ty = tid >> 5;
#pragma unroll
        for (int j = 0; j < 32; j += 8)
            tile[ty + j][tx] = W2[(size_t)(r0 + ty + j) * 1024 + c0 + tx];
        __syncthreads();
#pragma unroll
        for (int j = 0; j < 32; j += 8)
            g_W2T[(size_t)(c0 + ty + j) * 512 + r0 + tx] = tile[tx][ty + j];
    } else if (q < 29696) {                           // thresholds
        int idx = (q - 5120) * 256 + tid;
        float T = (idx < 1536 * 2048) ? T0c : T1c;
        float uu = u[idx];
        g_TH[idx] = T * (logf(uu) - log1pf(-uu));
    } else {                                          // cross weights
        int idx = (q - 29696) * 256 + tid;            // 0..98303
        int w = idx >> 10, rest = idx & 1023;
        int i = rest >> 5, j = rest & 31;
        float val = 0.f;
        if (i < j) {
            int a = ids[w * 32 + i], b = ids[w * 32 + j];
            if ((a < NH) != (b < NH)) {
                int o = (a < NH) ? (b - NH) : (a - NH);
                int n = (a < NH) ? a : b;
                val = W2[(size_t)o * NH + n];
            }
        }
        g_CW[idx] = val;
    }
}

// ---------------------------------------------------------------------------
// FP32 GEMM: 128x64 tile, 256 threads, 8x4 microtile, 2 CTAs/SM. (unchanged)
// ---------------------------------------------------------------------------
__global__ void __launch_bounds__(256, 2) gemm_bias_k(
    const float* __restrict__ A, const float* __restrict__ Bm,
    const float* __restrict__ bias, float* __restrict__ C,
    int M, int N, int K)
{
    __shared__ float As[16][132];
    __shared__ float Bs[16][72];
    int t  = threadIdx.x;
    int tx = t & 15, ty = t >> 4;
    int m0 = blockIdx.y * 128, n0 = blockIdx.x * 64;

    int ar = t >> 2;
    int ak = (t & 3) * 4;
    int bk = t >> 4;
    int bc = (t & 15) * 4;

    ull acc[8][2];
#pragma unroll
    for (int i = 0; i < 8; i++) { acc[i][0] = 0ull; acc[i][1] = 0ull; }

    for (int k0 = 0; k0 < K; k0 += 16) {
        float4 a0 = *(const float4*)&A[(size_t)(m0 + ar) * K + k0 + ak];
        float4 a1 = *(const float4*)&A[(size_t)(m0 + ar + 64) * K + k0 + ak];
        float4 b0 = *(const float4*)&Bm[(size_t)(k0 + bk) * N + n0 + bc];
        As[ak + 0][ar] = a0.x; As[ak + 1][ar] = a0.y;
        As[ak + 2][ar] = a0.z; As[ak + 3][ar] = a0.w;
        As[ak + 0][ar + 64] = a1.x; As[ak + 1][ar + 64] = a1.y;
        As[ak + 2][ar + 64] = a1.z; As[ak + 3][ar + 64] = a1.w;
        *(float4*)&Bs[bk][bc] = b0;
        __syncthreads();
#pragma unroll
        for (int k = 0; k < 16; ++k) {
            float4 av0 = *(const float4*)&As[k][ty * 8];
            float4 av1 = *(const float4*)&As[k][ty * 8 + 4];
            const ull* bpp = (const ull*)&Bs[k][tx * 4];
            ull bp0 = bpp[0], bp1 = bpp[1];
            float a[8] = { av0.x, av0.y, av0.z, av0.w,
                           av1.x, av1.y, av1.z, av1.w };
#pragma unroll
            for (int i = 0; i < 8; i++) {
                ull a2 = pack2f(a[i], a[i]);
                fma2(acc[i][0], bp0, a2);
                fma2(acc[i][1], bp1, a2);
            }
        }
        __syncthreads();
    }

    float4 bv = *(const float4*)&bias[n0 + tx * 4];
    float bb[4] = { bv.x, bv.y, bv.z, bv.w };
#pragma unroll
    for (int i = 0; i < 8; i++) {
        float4 o;
        o.x = __uint_as_float((unsigned)acc[i][0]) + bb[0];
        o.y = __uint_as_float((unsigned)(acc[i][0] >> 32)) + bb[1];
        o.z = __uint_as_float((unsigned)acc[i][1]) + bb[2];
        o.w = __uint_as_float((unsigned)(acc[i][1] >> 32)) + bb[3];
        *(float4*)&C[(size_t)(m0 + ty * 8 + i) * N + n0 + tx * 4] = o;
    }
}

// ---------------------------------------------------------------------------
// Gibbs v5: window-batched. 256 blocks x 256 threads, 8 chains/block, 2/SM.
// 96 windows of 32 updates; 8 sequencer threads do triangular decisions;
// all threads apply rank-r corrections to register gaps.
// smem floats:
//  s_s[12288] | cw_s[1024] | bg_s[256] | d_s[256] | ids(ushort)[3072]->1536f |
//  upos(ushort)[3072]->1536f | lst(uchar)[3072]->768f | hw[96] | cnt[96]
// ---------------------------------------------------------------------------
#define SM_S    0
#define SM_CW   12288
#define SM_BG   13312
#define SM_D    13568
#define SM_IDS  13824
#define SM_UPOS 15360
#define SM_LST  16896
#define SM_HW   17664
#define SM_CNT  17760
#define SMEM_FLOATS 17856
#define SMEM_BYTES  (SMEM_FLOATS * 4)

__global__ void __launch_bounds__(256, 2) gibbs_k(
    const float* __restrict__ x, const float* __restrict__ s1i,
    const float* __restrict__ s2i, const float* __restrict__ W2,
    const int* __restrict__ ids, float* __restrict__ out)
{
    extern __shared__ float sm[];
    float* s_s  = sm + SM_S;
    float* cw_s = sm + SM_CW;
    float* bg_s = sm + SM_BG;
    float* d_s  = sm + SM_D;
    unsigned short* ids_s = (unsigned short*)(sm + SM_IDS);
    unsigned short* upos  = (unsigned short*)(sm + SM_UPOS);
    unsigned char*  lst_s = (unsigned char*)(sm + SM_LST);
    unsigned* hw_s  = (unsigned*)(sm + SM_HW);
    unsigned* cnt_s = (unsigned*)(sm + SM_CNT);

    int tid = threadIdx.x, lane = tid & 31, wid = tid >> 5;
    int c0  = blockIdx.x * 8;

    for (int i = tid; i < NTOT; i += 256) ids_s[i] = (unsigned short)ids[i];
    __syncthreads();

    // hword per window (bit j = 1 iff unit is hidden)
    for (int g = wid; g < NWIN; g += 8) {
        int v = ids_s[g * 32 + lane];
        unsigned m = __ballot_sync(0xffffffffu, v < NH);
        if (lane == 0) hw_s[g] = m;
    }
    // per-window ordered lists: H positions first, then O positions
    for (int w = tid; w < NWIN; w += 256) {
        int hc = 0;
        for (int j = 0; j < 32; j++)
            if (ids_s[w * 32 + j] < NH) lst_s[w * 32 + hc++] = (unsigned char)j;
        cnt_s[w] = hc;
        int oc = hc;
        for (int j = 0; j < 32; j++)
            if (ids_s[w * 32 + j] >= NH) lst_s[w * 32 + oc++] = (unsigned char)j;
    }
    // position of each unit per sweep
    for (int p = tid; p < NTOT; p += 256) {
        int n = ids_s[p];
        upos[n + (p >= 1536 ? 1536 : 0)] = (unsigned short)p;
    }
    // state floats s_s[n*8+c]
    for (int i = tid; i < 1536; i += 256) {
#pragma unroll
        for (int c = 0; c < 8; c++) {
            float v = (i < NH) ? s1i[(size_t)(c0 + c) * NH + i]
                               : s2i[(size_t)(c0 + c) * NOUT + (i - NH)];
            s_s[i * 8 + c] = (v > 0.5f) ? 1.f : 0.f;
        }
    }

    // register gaps
    ull rH[4][4], rO[2][4];
#pragma unroll
    for (int u = 0; u < 4; u++)
#pragma unroll
        for (int p = 0; p < 4; p++)
            rH[u][p] = pack2f(g_gapH[(size_t)(c0 + 2 * p) * NH + 4 * tid + u],
                              g_gapH[(size_t)(c0 + 2 * p + 1) * NH + 4 * tid + u]);
#pragma unroll
    for (int v = 0; v < 2; v++)
#pragma unroll
        for (int p = 0; p < 4; p++)
            rO[v][p] = pack2f(g_gapO[(size_t)(c0 + 2 * p) * NOUT + 2 * tid + v],
                              g_gapO[(size_t)(c0 + 2 * p + 1) * NOUT + 2 * tid + v]);
    __syncthreads();

    // my 12 owned positions (4 H units x2 sweeps, 2 O units x2 sweeps)
    int mypos[12];
#pragma unroll
    for (int k = 0; k < 4; k++) {
        mypos[k]     = upos[4 * tid + k];
        mypos[k + 4] = upos[4 * tid + k + 1536];
    }
#pragma unroll
    for (int k = 0; k < 2; k++) {
        mypos[8 + k]  = upos[NH + 2 * tid + k];
        mypos[10 + k] = upos[NH + 2 * tid + k + 1536];
    }

    // stage window 0 base gaps
#define STAGE_WIN(NBASE)                                                     \
    {                                                                        \
        _Pragma("unroll")                                                    \
        for (int k = 0; k < 12; k++) {                                       \
            int pos = mypos[k];                                              \
            if (pos >= (NBASE) && pos < (NBASE) + 32) {                      \
                int j = pos - (NBASE);                                       \
                ull* bq = (ull*)bg_s + j * 4;                                \
                if (k < 8) {                                                 \
                    int u = k & 3;                                           \
                    _Pragma("unroll")                                        \
                    for (int p = 0; p < 4; p++) bq[p] = rH[u][p];            \
                } else {                                                     \
                    int v = k & 1;                                           \
                    _Pragma("unroll")                                        \
                    for (int p = 0; p < 4; p++) bq[p] = rO[v][p];            \
                }                                                            \
            }                                                                \
        }                                                                    \
    }
    STAGE_WIN(0)
    // load cw(0), prefetch th(0)
    ((float4*)cw_s)[tid] = ((const float4*)g_CW)[tid];
    if (tid < 32)
        asm volatile("prefetch.global.L1 [%0];"
                     :: "l"(&g_TH[(size_t)tid * B_ + c0]));
    __syncthreads();

    for (int w = 0; w < NWIN; w++) {
        int base = w * 32;

        // ===== sequencer phase =====
        if (tid < 8) {
            int c = tid;
            unsigned hword = hw_s[w];
            const float* thp = g_TH + (size_t)base * B_ + c0 + c;
            unsigned dP = 0, dM = 0;
#pragma unroll 1
            for (int j = 0; j < 32; j++) {
                int n = ids_s[base + j];
                float g = bg_s[j * 8 + c];
                unsigned below = (j == 0) ? 0u : (0xffffffffu >> (32 - j));
                unsigned cm = (((hword >> j) & 1u) ? ~hword : hword) & below;
                unsigned act = cm & (dP | dM);
                while (act) {
                    int i = __ffs(act) - 1;
                    act &= act - 1;
                    float cv = cw_s[i * 32 + j];
                    g = ((dP >> i) & 1u) ? (g + cv) : (g - cv);
                }
                float th = __ldg(thp + (size_t)j * B_);
                float ov = s_s[n * 8 + c];
                float nv = (g > th) ? 1.f : 0.f;
                float d = nv - ov;
                d_s[j * 8 + c] = d;
                s_s[n * 8 + c] = nv;
                if (d > 0.5f) dP |= 1u << j;
                else if (d < -0.5f) dM |= 1u << j;
            }
        } else {
            // prefetch this window's weight slices (own future addresses)
            for (int k = 0; k < 32; k++) {
                int j = lst_s[w * 32 + k];
                int n = ids_s[base + j];
                const float* wp = (n < NH)
                    ? (g_W2T + (size_t)n * NOUT + 2 * tid)
                    : (W2 + (size_t)(n - NH) * NH + 4 * tid);
                asm volatile("prefetch.global.L1 [%0];" :: "l"(wp));
            }
            // prefetch next window's thresholds
            if (tid < 40 && w + 1 < NWIN)
                asm volatile("prefetch.global.L1 [%0];"
                             :: "l"(&g_TH[(size_t)(base + 32 + tid - 8) * B_ + c0]));
        }
        __syncthreads();

        // ===== apply phase =====
        int hcnt = cnt_s[w];
        for (int k = 0; k < hcnt; k++) {
            int j = lst_s[w * 32 + k];
            int n = ids_s[base + j];
            float2 wv = __ldg((const float2*)(g_W2T + (size_t)n * NOUT + 2 * tid));
            ull w0 = pack2f(wv.x, wv.x);
            ull w1 = pack2f(wv.y, wv.y);
            const ull* dp = (const ull*)(d_s + j * 8);
#pragma unroll
            for (int p = 0; p < 4; p++) {
                ull d = dp[p];
                fma2(rO[0][p], d, w0);
                fma2(rO[1][p], d, w1);
            }
        }
        for (int k = hcnt; k < 32; k++) {
            int j = lst_s[w * 32 + k];
            int o = ids_s[base + j] - NH;
            float4 wv = __ldg((const float4*)(W2 + (size_t)o * NH + 4 * tid));
            ull w0 = pack2f(wv.x, wv.x);
            ull w1 = pack2f(wv.y, wv.y);
            ull w2_ = pack2f(wv.z, wv.z);
            ull w3 = pack2f(wv.w, wv.w);
            const ull* dp = (const ull*)(d_s + j * 8);
#pragma unroll
            for (int p = 0; p < 4; p++) {
                ull d = dp[p];
                fma2(rH[0][p], d, w0);
                fma2(rH[1][p], d, w1);
                fma2(rH[2][p], d, w2_);
                fma2(rH[3][p], d, w3);
            }
        }
        // stage next window's base gaps + cross weights
        if (w + 1 < NWIN) {
            int nb = base + 32;
            STAGE_WIN(nb)
            ((float4*)cw_s)[tid] =
                ((const float4*)(g_CW + (size_t)(w + 1) * 1024))[tid];
        }
        __syncthreads();
    }

    // ===== epilogue =====
#pragma unroll
    for (int c = 0; c < 8; c++) {
        int b = c0 + c;
        size_t rb4 = (size_t)b * 640;
        ((float4*)out)[rb4 + tid] = ((const float4*)x)[(size_t)b * 256 + tid];
        float4 v1;
        v1.x = s_s[(4 * tid + 0) * 8 + c];
        v1.y = s_s[(4 * tid + 1) * 8 + c];
        v1.z = s_s[(4 * tid + 2) * 8 + c];
        v1.w = s_s[(4 * tid + 3) * 8 + c];
        ((float4*)out)[rb4 + 256 + tid] = v1;
        if (tid < 128) {
            float4 v2;
            v2.x = s_s[(1024 + 4 * tid + 0) * 8 + c];
            v2.y = s_s[(1024 + 4 * tid + 1) * 8 + c];
            v2.z = s_s[(1024 + 4 * tid + 2) * 8 + c];
            v2.w = s_s[(1024 + 4 * tid + 3) * 8 + c];
            ((float4*)out)[rb4 + 512 + tid] = v2;
        }
    }
}

// ---------------------------------------------------------------------------
extern "C" void kernel_launch(void* const* d_in, const int* in_sizes, int n_in,
                              void* d_out, int out_size)
{
    const float* x   = (const float*)d_in[0];
    const float* s1i = (const float*)d_in[1];
    const float* s2i = (const float*)d_in[2];
    const float* W1  = (const float*)d_in[3];
    const float* b1  = (const float*)d_in[4];
    const float* W2  = (const float*)d_in[5];
    const float* b2  = (const float*)d_in[6];
    const float* u   = (const float*)d_in[7];
    const int*   ids = (const int*)d_in[8];
    float* out = (float*)d_out;

    float *pA, *pWH, *pW2T, *pGH, *pGO;
    cudaGetSymbolAddress((void**)&pA,   g_A);
    cudaGetSymbolAddress((void**)&pWH,  g_WH);
    cudaGetSymbolAddress((void**)&pW2T, g_W2T);
    cudaGetSymbolAddress((void**)&pGH,  g_gapH);
    cudaGetSymbolAddress((void**)&pGO,  g_gapO);

    prep_k     <<<30080, 256>>>(x, s2i, W1, W2, u, ids);
    gemm_bias_k<<<dim3(16, 16), 256>>>(pA,  pWH,  b1, pGH, 2048, 1024, 1536);
    gemm_bias_k<<<dim3(8, 16),  256>>>(s1i, pW2T, b2, pGO, 2048, 512, 1024);

    cudaFuncSetAttribute(gibbs_k, cudaFuncAttributeMaxDynamicSharedMemorySize,
                         SMEM_BYTES);
    gibbs_k<<<256, 256, SMEM_BYTES>>>(x, s1i, s2i, W2, ids, out);
}

// round 13
// speedup vs baseline: 1.3828x; 1.3728x over previous
#include <cuda_runtime.h>
#include <cuda_bf16.h>
#include <math.h>

#define B_    2048
#define NIN   1024
#define NH    1024
#define NOUT  512
#define NTOT  3072
#define KCAT  1536
#define NWIN  96
#define T0c   2.0f
#define T1c   1.6374615061559636f   // 2/exp(0.2)

typedef unsigned long long ull;

// ---- device scratch (no runtime allocation allowed) ----
__device__ float g_A[B_ * KCAT];        // [x, s2_init] packed
__device__ float g_WH[KCAT * NH];       // [W1^T ; W2]
__device__ float g_W2T[NH * NOUT];      // W2 transposed
__device__ float g_TH[NTOT * B_];       // thresholds T*logit(u), layout [t][b]
__device__ float g_gapH[B_ * NH];       // init hidden gaps
__device__ float g_gapO[B_ * NOUT];     // init output gaps
__device__ float g_CW[NWIN * 1024];     // cross weights per window [w][i][j]

// ---------------------------------------------------------------------------
// f32x2 helpers
// ---------------------------------------------------------------------------
__device__ __forceinline__ ull pack2f(float lo, float hi) {
    ull r;
    asm("mov.b64 %0, {%1, %2};" : "=l"(r)
        : "r"(__float_as_uint(lo)), "r"(__float_as_uint(hi)));
    return r;
}
__device__ __forceinline__ void fma2(ull& acc, ull a, ull b) {
    asm("fma.rn.f32x2 %0, %1, %2, %0;" : "+l"(acc) : "l"(a), "l"(b));
}

// ---------------------------------------------------------------------------
// Fused prep: segmented grid. (unchanged)
// ---------------------------------------------------------------------------
__global__ void __launch_bounds__(256) prep_k(
    const float* __restrict__ x, const float* __restrict__ s2i,
    const float* __restrict__ W1, const float* __restrict__ W2,
    const float* __restrict__ u, const int* __restrict__ ids)
{
    __shared__ float tile[32][33];
    int q = blockIdx.x, tid = threadIdx.x;

    if (q < 3072) {                                   // pack_A
        int idx = q * 256 + tid;
        int b = idx / 384, c = idx % 384;
        float4 v = (c < 256) ? ((const float4*)x)[(size_t)b * 256 + c]
                             : ((const float4*)s2i)[(size_t)b * 128 + (c - 256)];
        ((float4*)g_A)[idx] = v;
    } else if (q < 4096) {                            // transpose W1
        int r = q - 3072;
        int c0 = (r & 31) * 32, r0 = (r >> 5) * 32;
        int tx = tid & 31, ty = tid >> 5;
#pragma unroll
        for (int j = 0; j < 32; j += 8)
            tile[ty + j][tx] = W1[(size_t)(r0 + ty + j) * 1024 + c0 + tx];
        __syncthreads();
#pragma unroll
        for (int j = 0; j < 32; j += 8)
            g_WH[(size_t)(c0 + ty + j) * 1024 + r0 + tx] = tile[tx][ty + j];
    } else if (q < 4608) {                            // copy W2
        int idx = (q - 4096) * 256 + tid;
        ((float4*)(g_WH + 1024 * 1024))[idx] = ((const float4*)W2)[idx];
    } else if (q < 5120) {                            // transpose W2
        int r = q - 4608;
        int c0 = (r & 31) * 32, r0 = (r >> 5) * 32;
        int tx = tid & 31, ty = tid >> 5;
#pragma unroll
        for (int j = 0; j < 32; j += 8)
            tile[ty + j][tx] = W2[(size_t)(r0 + ty + j) * 1024 + c0 + tx];
        __syncthreads();
#pragma unroll
        for (int j = 0; j < 32; j += 8)
            g_W2T[(size_t)(c0 + ty + j) * 512 + r0 + tx] = tile[tx][ty + j];
    } else if (q < 29696) {                           // thresholds
        int idx = (q - 5120) * 256 + tid;
        float T = (idx < 1536 * 2048) ? T0c : T1c;
        float uu = u[idx];
        g_TH[idx] = T * (logf(uu) - log1pf(-uu));
    } else {                                          // cross weights
        int idx = (q - 29696) * 256 + tid;
        int w = idx >> 10, rest = idx & 1023;
        int i = rest >> 5, j = rest & 31;
        float val = 0.f;
        if (i < j) {
            int a = ids[w * 32 + i], b = ids[w * 32 + j];
            if ((a < NH) != (b < NH)) {
                int o = (a < NH) ? (b - NH) : (a - NH);
                int n = (a < NH) ? a : b;
                val = W2[(size_t)o * NH + n];
            }
        }
        g_CW[idx] = val;
    }
}

// ---------------------------------------------------------------------------
// FP32 GEMM: 128x64 tile, 256 threads, 8x4 microtile, 2 CTAs/SM. (unchanged)
// ---------------------------------------------------------------------------
__global__ void __launch_bounds__(256, 2) gemm_bias_k(
    const float* __restrict__ A, const float* __restrict__ Bm,
    const float* __restrict__ bias, float* __restrict__ C,
    int M, int N, int K)
{
    __shared__ float As[16][132];
    __shared__ float Bs[16][72];
    int t  = threadIdx.x;
    int tx = t & 15, ty = t >> 4;
    int m0 = blockIdx.y * 128, n0 = blockIdx.x * 64;

    int ar = t >> 2;
    int ak = (t & 3) * 4;
    int bk = t >> 4;
    int bc = (t & 15) * 4;

    ull acc[8][2];
#pragma unroll
    for (int i = 0; i < 8; i++) { acc[i][0] = 0ull; acc[i][1] = 0ull; }

    for (int k0 = 0; k0 < K; k0 += 16) {
        float4 a0 = *(const float4*)&A[(size_t)(m0 + ar) * K + k0 + ak];
        float4 a1 = *(const float4*)&A[(size_t)(m0 + ar + 64) * K + k0 + ak];
        float4 b0 = *(const float4*)&Bm[(size_t)(k0 + bk) * N + n0 + bc];
        As[ak + 0][ar] = a0.x; As[ak + 1][ar] = a0.y;
        As[ak + 2][ar] = a0.z; As[ak + 3][ar] = a0.w;
        As[ak + 0][ar + 64] = a1.x; As[ak + 1][ar + 64] = a1.y;
        As[ak + 2][ar + 64] = a1.z; As[ak + 3][ar + 64] = a1.w;
        *(float4*)&Bs[bk][bc] = b0;
        __syncthreads();
#pragma unroll
        for (int k = 0; k < 16; ++k) {
            float4 av0 = *(const float4*)&As[k][ty * 8];
            float4 av1 = *(const float4*)&As[k][ty * 8 + 4];
            const ull* bpp = (const ull*)&Bs[k][tx * 4];
            ull bp0 = bpp[0], bp1 = bpp[1];
            float a[8] = { av0.x, av0.y, av0.z, av0.w,
                           av1.x, av1.y, av1.z, av1.w };
#pragma unroll
            for (int i = 0; i < 8; i++) {
                ull a2 = pack2f(a[i], a[i]);
                fma2(acc[i][0], bp0, a2);
                fma2(acc[i][1], bp1, a2);
            }
        }
        __syncthreads();
    }

    float4 bv = *(const float4*)&bias[n0 + tx * 4];
    float bb[4] = { bv.x, bv.y, bv.z, bv.w };
#pragma unroll
    for (int i = 0; i < 8; i++) {
        float4 o;
        o.x = __uint_as_float((unsigned)acc[i][0]) + bb[0];
        o.y = __uint_as_float((unsigned)(acc[i][0] >> 32)) + bb[1];
        o.z = __uint_as_float((unsigned)acc[i][1]) + bb[2];
        o.w = __uint_as_float((unsigned)(acc[i][1] >> 32)) + bb[3];
        *(float4*)&C[(size_t)(m0 + ty * 8 + i) * N + n0 + tx * 4] = o;
    }
}

// ---------------------------------------------------------------------------
// Gibbs v6: window-batched, sequencer-per-warp.
// 256 blocks x 256 threads, 8 chains/block, 2 CTAs/SM.
// Sequencer for chain c = lane 0 of warp c (no cross-chain divergence).
// All staging/prefetch for window w+1 happens in apply(w).
// ---------------------------------------------------------------------------
#define SM_S    0
#define SM_CW   12288
#define SM_BG   13312
#define SM_D    13568
#define SM_TH   13824
#define SM_IDS  14080
#define SM_UORD 15616
#define SM_UPOS 17152
#define SM_HW   18688
#define SM_CNT  18784
#define SMEM_FLOATS 18880
#define SMEM_BYTES  (SMEM_FLOATS * 4)

__global__ void __launch_bounds__(256, 2) gibbs_k(
    const float* __restrict__ x, const float* __restrict__ s1i,
    const float* __restrict__ s2i, const float* __restrict__ W2,
    const int* __restrict__ ids, float* __restrict__ out)
{
    extern __shared__ float sm[];
    float* s_s   = sm + SM_S;
    float* cw_s  = sm + SM_CW;
    float* bg_s  = sm + SM_BG;
    float* d_s   = sm + SM_D;
    float* th_st = sm + SM_TH;
    unsigned short* ids_s = (unsigned short*)(sm + SM_IDS);
    unsigned short* uord  = (unsigned short*)(sm + SM_UORD);
    unsigned short* upos  = (unsigned short*)(sm + SM_UPOS);
    unsigned* hw_s  = (unsigned*)(sm + SM_HW);
    unsigned* cnt_s = (unsigned*)(sm + SM_CNT);

    int tid = threadIdx.x, lane = tid & 31, wid = tid >> 5;
    int c0  = blockIdx.x * 8;

    for (int i = tid; i < NTOT; i += 256) ids_s[i] = (unsigned short)ids[i];
    __syncthreads();

    // hword per window (bit j = 1 iff unit is hidden)
    for (int g = wid; g < NWIN; g += 8) {
        int v = ids_s[g * 32 + lane];
        unsigned m = __ballot_sync(0xffffffffu, v < NH);
        if (lane == 0) hw_s[g] = m;
    }
    // per-window ordered packed lists: H first then O, (j<<11)|n
    for (int w = tid; w < NWIN; w += 256) {
        int hc = 0;
        for (int j = 0; j < 32; j++) {
            int n = ids_s[w * 32 + j];
            if (n < NH) uord[w * 32 + hc++] = (unsigned short)((j << 11) | n);
        }
        cnt_s[w] = hc;
        int oc = hc;
        for (int j = 0; j < 32; j++) {
            int n = ids_s[w * 32 + j];
            if (n >= NH) uord[w * 32 + oc++] = (unsigned short)((j << 11) | n);
        }
    }
    // position of each unit per sweep
    for (int p = tid; p < NTOT; p += 256) {
        int n = ids_s[p];
        upos[n + (p >= 1536 ? 1536 : 0)] = (unsigned short)p;
    }
    // state floats s_s[n*8+c]
    for (int i = tid; i < 1536; i += 256) {
#pragma unroll
        for (int c = 0; c < 8; c++) {
            float v = (i < NH) ? s1i[(size_t)(c0 + c) * NH + i]
                               : s2i[(size_t)(c0 + c) * NOUT + (i - NH)];
            s_s[i * 8 + c] = (v > 0.5f) ? 1.f : 0.f;
        }
    }

    // register gaps
    ull rH[4][4], rO[2][4];
#pragma unroll
    for (int u = 0; u < 4; u++)
#pragma unroll
        for (int p = 0; p < 4; p++)
            rH[u][p] = pack2f(g_gapH[(size_t)(c0 + 2 * p) * NH + 4 * tid + u],
                              g_gapH[(size_t)(c0 + 2 * p + 1) * NH + 4 * tid + u]);
#pragma unroll
    for (int v = 0; v < 2; v++)
#pragma unroll
        for (int p = 0; p < 4; p++)
            rO[v][p] = pack2f(g_gapO[(size_t)(c0 + 2 * p) * NOUT + 2 * tid + v],
                              g_gapO[(size_t)(c0 + 2 * p + 1) * NOUT + 2 * tid + v]);
    __syncthreads();

    // my 12 owned positions
    int mypos[12];
#pragma unroll
    for (int k = 0; k < 4; k++) {
        mypos[k]     = upos[4 * tid + k];
        mypos[k + 4] = upos[4 * tid + k + 1536];
    }
#pragma unroll
    for (int k = 0; k < 2; k++) {
        mypos[8 + k]  = upos[NH + 2 * tid + k];
        mypos[10 + k] = upos[NH + 2 * tid + k + 1536];
    }

#define STAGE_WIN(NBASE)                                                     \
    {                                                                        \
        _Pragma("unroll")                                                    \
        for (int k = 0; k < 12; k++) {                                       \
            int pos = mypos[k];                                              \
            if (pos >= (NBASE) && pos < (NBASE) + 32) {                      \
                int j = pos - (NBASE);                                       \
                ull* bq = (ull*)bg_s + j * 4;                                \
                if (k < 8) {                                                 \
                    int u = k & 3;                                           \
                    _Pragma("unroll")                                        \
                    for (int p = 0; p < 4; p++) bq[p] = rH[u][p];            \
                } else {                                                     \
                    int v = k & 1;                                           \
                    _Pragma("unroll")                                        \
                    for (int p = 0; p < 4; p++) bq[p] = rO[v][p];            \
                }                                                            \
            }                                                                \
        }                                                                    \
    }

    // ---- pre-loop staging for window 0 ----
    STAGE_WIN(0)
    ((float4*)cw_s)[tid] = ((const float4*)g_CW)[tid];
    if (tid < 64) {
        int j = tid >> 1, h = tid & 1;
        *(float4*)&th_st[j * 8 + 4 * h] =
            *(const float4*)&g_TH[(size_t)j * B_ + c0 + 4 * h];
    }
#pragma unroll
    for (int kk = 0; kk < 4; kk++) {
        int v = uord[wid * 4 + kk];
        int n = v & 0x7FF;
        const float* rp; int nl;
        if (n < NH) { rp = g_W2T + (size_t)n * NOUT; nl = 16; }
        else        { rp = W2 + (size_t)(n - NH) * NH; nl = 32; }
        if (lane < nl)
            asm volatile("prefetch.global.L1 [%0];" :: "l"(rp + lane * 32));
    }
    __syncthreads();

    for (int w = 0; w < NWIN; w++) {
        int base = w * 32;

        // ===== sequencer: lane 0 of warp c handles chain c =====
        if (lane == 0) {
            int c = wid;
            unsigned hword = hw_s[w];
            unsigned dP = 0, dM = 0;
            for (int j = 0; j < 32; j++) {
                int n = ids_s[base + j];
                float g = bg_s[j * 8 + c];
                unsigned below = (1u << j) - 1u;
                unsigned opp = ((hword >> j) & 1u) ? ~hword : hword;
                unsigned act = opp & below & (dP | dM);
                while (act) {
                    int i = __ffs(act) - 1;
                    act &= act - 1;
                    float cv = cw_s[i * 32 + j];
                    g = ((dP >> i) & 1u) ? (g + cv) : (g - cv);
                }
                float th = th_st[j * 8 + c];
                float ov = s_s[n * 8 + c];
                float nv = (g > th) ? 1.f : 0.f;
                float d = nv - ov;
                d_s[j * 8 + c] = d;
                s_s[n * 8 + c] = nv;
                if (d > 0.5f) dP |= 1u << j;
                else if (d < -0.5f) dM |= 1u << j;
            }
        }
        __syncthreads();

        // ===== apply phase =====
        int hcnt = cnt_s[w];
        for (int k = 0; k < hcnt; k++) {
            int v = uord[base + k];
            int n = v & 0x7FF, j = v >> 11;
            float2 wv = __ldg((const float2*)(g_W2T + (size_t)n * NOUT + 2 * tid));
            ull w0 = pack2f(wv.x, wv.x);
            ull w1 = pack2f(wv.y, wv.y);
            const ull* dp = (const ull*)(d_s + j * 8);
#pragma unroll
            for (int p = 0; p < 4; p++) {
                ull d = dp[p];
                fma2(rO[0][p], d, w0);
                fma2(rO[1][p], d, w1);
            }
        }
        for (int k = hcnt; k < 32; k++) {
            int v = uord[base + k];
            int o = (v & 0x7FF) - NH, j = v >> 11;
            float4 wv = __ldg((const float4*)(W2 + (size_t)o * NH + 4 * tid));
            ull w0 = pack2f(wv.x, wv.x);
            ull w1 = pack2f(wv.y, wv.y);
            ull w2_ = pack2f(wv.z, wv.z);
            ull w3 = pack2f(wv.w, wv.w);
            const ull* dp = (const ull*)(d_s + j * 8);
#pragma unroll
            for (int p = 0; p < 4; p++) {
                ull d = dp[p];
                fma2(rH[0][p], d, w0);
                fma2(rH[1][p], d, w1);
                fma2(rH[2][p], d, w2_);
                fma2(rH[3][p], d, w3);
            }
        }

        // ===== stage/prefetch for next window =====
        if (w + 1 < NWIN) {
            int nb = base + 32;
            STAGE_WIN(nb)
            ((float4*)cw_s)[tid] =
                ((const float4*)(g_CW + (size_t)(w + 1) * 1024))[tid];
            if (tid < 64) {
                int j = tid >> 1, h = tid & 1;
                *(float4*)&th_st[j * 8 + 4 * h] =
                    *(const float4*)&g_TH[(size_t)(nb + j) * B_ + c0 + 4 * h];
            }
#pragma unroll
            for (int kk = 0; kk < 4; kk++) {
                int v = uord[nb + wid * 4 + kk];
                int n = v & 0x7FF;
                const float* rp; int nl;
                if (n < NH) { rp = g_W2T + (size_t)n * NOUT; nl = 16; }
                else        { rp = W2 + (size_t)(n - NH) * NH; nl = 32; }
                if (lane < nl)
                    asm volatile("prefetch.global.L1 [%0];" :: "l"(rp + lane * 32));
            }
        }
        __syncthreads();
    }

    // ===== epilogue =====
#pragma unroll
    for (int c = 0; c < 8; c++) {
        int b = c0 + c;
        size_t rb4 = (size_t)b * 640;
        ((float4*)out)[rb4 + tid] = ((const float4*)x)[(size_t)b * 256 + tid];
        float4 v1;
        v1.x = s_s[(4 * tid + 0) * 8 + c];
        v1.y = s_s[(4 * tid + 1) * 8 + c];
        v1.z = s_s[(4 * tid + 2) * 8 + c];
        v1.w = s_s[(4 * tid + 3) * 8 + c];
        ((float4*)out)[rb4 + 256 + tid] = v1;
        if (tid < 128) {
            float4 v2;
            v2.x = s_s[(1024 + 4 * tid + 0) * 8 + c];
            v2.y = s_s[(1024 + 4 * tid + 1) * 8 + c];
            v2.z = s_s[(1024 + 4 * tid + 2) * 8 + c];
            v2.w = s_s[(1024 + 4 * tid + 3) * 8 + c];
            ((float4*)out)[rb4 + 512 + tid] = v2;
        }
    }
}

// ---------------------------------------------------------------------------
extern "C" void kernel_launch(void* const* d_in, const int* in_sizes, int n_in,
                              void* d_out, int out_size)
{
    const float* x   = (const float*)d_in[0];
    const float* s1i = (const float*)d_in[1];
    const float* s2i = (const float*)d_in[2];
    const float* W1  = (const float*)d_in[3];
    const float* b1  = (const float*)d_in[4];
    const float* W2  = (const float*)d_in[5];
    const float* b2  = (const float*)d_in[6];
    const float* u   = (const float*)d_in[7];
    const int*   ids = (const int*)d_in[8];
    float* out = (float*)d_out;

    float *pA, *pWH, *pW2T, *pGH, *pGO;
    cudaGetSymbolAddress((void**)&pA,   g_A);
    cudaGetSymbolAddress((void**)&pWH,  g_WH);
    cudaGetSymbolAddress((void**)&pW2T, g_W2T);
    cudaGetSymbolAddress((void**)&pGH,  g_gapH);
    cudaGetSymbolAddress((void**)&pGO,  g_gapO);

    prep_k     <<<30080, 256>>>(x, s2i, W1, W2, u, ids);
    gemm_bias_k<<<dim3(16, 16), 256>>>(pA,  pWH,  b1, pGH, 2048, 1024, 1536);
    gemm_bias_k<<<dim3(8, 16),  256>>>(s1i, pW2T, b2, pGO, 2048, 512, 1024);

    cudaFuncSetAttribute(gibbs_k, cudaFuncAttributeMaxDynamicSharedMemorySize,
                         SMEM_BYTES);
    gibbs_k<<<256, 256, SMEM_BYTES>>>(x, s1i, s2i, W2, ids, out);
}

// round 14
// speedup vs baseline: 2.8548x; 2.0644x over previous
#include <cuda_runtime.h>
#include <cuda_bf16.h>
#include <math.h>

#define B_    2048
#define NIN   1024
#define NH    1024
#define NOUT  512
#define NTOT  3072
#define KCAT  1536
#define NWIN  96
#define T0c   2.0f
#define T1c   1.6374615061559636f   // 2/exp(0.2)

typedef unsigned long long ull;

// ---- device scratch (no runtime allocation allowed) ----
__device__ float g_A[B_ * KCAT];        // [x, s2_init] packed
__device__ float g_WH[KCAT * NH];       // [W1^T ; W2]
__device__ float g_W2T[NH * NOUT];      // W2 transposed
__device__ float g_TH[NTOT * B_];       // thresholds T*logit(u), layout [t][b]
__device__ float g_gapH[B_ * NH];       // init hidden gaps
__device__ float g_gapO[B_ * NOUT];     // init output gaps
__device__ float g_CW[NWIN * 1024];     // cross weights per window [w][i][j]

// ---------------------------------------------------------------------------
// f32x2 helpers
// ---------------------------------------------------------------------------
__device__ __forceinline__ ull pack2f(float lo, float hi) {
    ull r;
    asm("mov.b64 %0, {%1, %2};" : "=l"(r)
        : "r"(__float_as_uint(lo)), "r"(__float_as_uint(hi)));
    return r;
}
__device__ __forceinline__ void fma2(ull& acc, ull a, ull b) {
    asm("fma.rn.f32x2 %0, %1, %2, %0;" : "+l"(acc) : "l"(a), "l"(b));
}

// ---------------------------------------------------------------------------
// Fused prep: segmented grid. (unchanged)
// ---------------------------------------------------------------------------
__global__ void __launch_bounds__(256) prep_k(
    const float* __restrict__ x, const float* __restrict__ s2i,
    const float* __restrict__ W1, const float* __restrict__ W2,
    const float* __restrict__ u, const int* __restrict__ ids)
{
    __shared__ float tile[32][33];
    int q = blockIdx.x, tid = threadIdx.x;

    if (q < 3072) {                                   // pack_A
        int idx = q * 256 + tid;
        int b = idx / 384, c = idx % 384;
        float4 v = (c < 256) ? ((const float4*)x)[(size_t)b * 256 + c]
                             : ((const float4*)s2i)[(size_t)b * 128 + (c - 256)];
        ((float4*)g_A)[idx] = v;
    } else if (q < 4096) {                            // transpose W1
        int r = q - 3072;
        int c0 = (r & 31) * 32, r0 = (r >> 5) * 32;
        int tx = tid & 31, ty = tid >> 5;
#pragma unroll
        for (int j = 0; j < 32; j += 8)
            tile[ty + j][tx] = W1[(size_t)(r0 + ty + j) * 1024 + c0 + tx];
        __syncthreads();
#pragma unroll
        for (int j = 0; j < 32; j += 8)
            g_WH[(size_t)(c0 + ty + j) * 1024 + r0 + tx] = tile[tx][ty + j];
    } else if (q < 4608) {                            // copy W2
        int idx = (q - 4096) * 256 + tid;
        ((float4*)(g_WH + 1024 * 1024))[idx] = ((const float4*)W2)[idx];
    } else if (q < 5120) {                            // transpose W2
        int r = q - 4608;
        int c0 = (r & 31) * 32, r0 = (r >> 5) * 32;
        int tx = tid & 31, ty = tid >> 5;
#pragma unroll
        for (int j = 0; j < 32; j += 8)
            tile[ty + j][tx] = W2[(size_t)(r0 + ty + j) * 1024 + c0 + tx];
        __syncthreads();
#pragma unroll
        for (int j = 0; j < 32; j += 8)
            g_W2T[(size_t)(c0 + ty + j) * 512 + r0 + tx] = tile[tx][ty + j];
    } else if (q < 29696) {                           // thresholds
        int idx = (q - 5120) * 256 + tid;
        float T = (idx < 1536 * 2048) ? T0c : T1c;
        float uu = u[idx];
        g_TH[idx] = T * (logf(uu) - log1pf(-uu));
    } else {                                          // cross weights
        int idx = (q - 29696) * 256 + tid;
        int w = idx >> 10, rest = idx & 1023;
        int i = rest >> 5, j = rest & 31;
        float val = 0.f;
        if (i < j) {
            int a = ids[w * 32 + i], b = ids[w * 32 + j];
            if ((a < NH) != (b < NH)) {
                int o = (a < NH) ? (b - NH) : (a - NH);
                int n = (a < NH) ? a : b;
                val = W2[(size_t)o * NH + n];
            }
        }
        g_CW[idx] = val;
    }
}

// ---------------------------------------------------------------------------
// FP32 GEMM: 128x64 tile, 256 threads, 8x4 microtile, 2 CTAs/SM. (unchanged)
// ---------------------------------------------------------------------------
__global__ void __launch_bounds__(256, 2) gemm_bias_k(
    const float* __restrict__ A, const float* __restrict__ Bm,
    const float* __restrict__ bias, float* __restrict__ C,
    int M, int N, int K)
{
    __shared__ float As[16][132];
    __shared__ float Bs[16][72];
    int t  = threadIdx.x;
    int tx = t & 15, ty = t >> 4;
    int m0 = blockIdx.y * 128, n0 = blockIdx.x * 64;

    int ar = t >> 2;
    int ak = (t & 3) * 4;
    int bk = t >> 4;
    int bc = (t & 15) * 4;

    ull acc[8][2];
#pragma unroll
    for (int i = 0; i < 8; i++) { acc[i][0] = 0ull; acc[i][1] = 0ull; }

    for (int k0 = 0; k0 < K; k0 += 16) {
        float4 a0 = *(const float4*)&A[(size_t)(m0 + ar) * K + k0 + ak];
        float4 a1 = *(const float4*)&A[(size_t)(m0 + ar + 64) * K + k0 + ak];
        float4 b0 = *(const float4*)&Bm[(size_t)(k0 + bk) * N + n0 + bc];
        As[ak + 0][ar] = a0.x; As[ak + 1][ar] = a0.y;
        As[ak + 2][ar] = a0.z; As[ak + 3][ar] = a0.w;
        As[ak + 0][ar + 64] = a1.x; As[ak + 1][ar + 64] = a1.y;
        As[ak + 2][ar + 64] = a1.z; As[ak + 3][ar + 64] = a1.w;
        *(float4*)&Bs[bk][bc] = b0;
        __syncthreads();
#pragma unroll
        for (int k = 0; k < 16; ++k) {
            float4 av0 = *(const float4*)&As[k][ty * 8];
            float4 av1 = *(const float4*)&As[k][ty * 8 + 4];
            const ull* bpp = (const ull*)&Bs[k][tx * 4];
            ull bp0 = bpp[0], bp1 = bpp[1];
            float a[8] = { av0.x, av0.y, av0.z, av0.w,
                           av1.x, av1.y, av1.z, av1.w };
#pragma unroll
            for (int i = 0; i < 8; i++) {
                ull a2 = pack2f(a[i], a[i]);
                fma2(acc[i][0], bp0, a2);
                fma2(acc[i][1], bp1, a2);
            }
        }
        __syncthreads();
    }

    float4 bv = *(const float4*)&bias[n0 + tx * 4];
    float bb[4] = { bv.x, bv.y, bv.z, bv.w };
#pragma unroll
    for (int i = 0; i < 8; i++) {
        float4 o;
        o.x = __uint_as_float((unsigned)acc[i][0]) + bb[0];
        o.y = __uint_as_float((unsigned)(acc[i][0] >> 32)) + bb[1];
        o.z = __uint_as_float((unsigned)acc[i][1]) + bb[2];
        o.w = __uint_as_float((unsigned)(acc[i][1] >> 32)) + bb[3];
        *(float4*)&C[(size_t)(m0 + ty * 8 + i) * N + n0 + tx * 4] = o;
    }
}

// ---------------------------------------------------------------------------
// Gibbs v7: window-batched, push-model warp-parallel sequencer.
// 256 blocks x 256 threads, 8 chains/block, 2 CTAs/SM.
// Warp c = chain c; lane j = update j within the window. Corrections are
// pushed forward with one fmaf per lane per update (cw has structural zeros).
// ---------------------------------------------------------------------------
#define SM_S    0
#define SM_CW   12288
#define SM_BG   13312
#define SM_D    13568
#define SM_TH   13824
#define SM_IDS  14080
#define SM_UORD 15616
#define SM_UPOS 17152
#define SM_CNT  18688
#define SMEM_FLOATS 18784
#define SMEM_BYTES  (SMEM_FLOATS * 4)

__global__ void __launch_bounds__(256, 2) gibbs_k(
    const float* __restrict__ x, const float* __restrict__ s1i,
    const float* __restrict__ s2i, const float* __restrict__ W2,
    const int* __restrict__ ids, float* __restrict__ out)
{
    extern __shared__ float sm[];
    float* s_s   = sm + SM_S;
    float* cw_s  = sm + SM_CW;
    float* bg_s  = sm + SM_BG;
    float* d_s   = sm + SM_D;
    float* th_st = sm + SM_TH;
    unsigned short* ids_s = (unsigned short*)(sm + SM_IDS);
    unsigned short* uord  = (unsigned short*)(sm + SM_UORD);
    unsigned short* upos  = (unsigned short*)(sm + SM_UPOS);
    unsigned* cnt_s = (unsigned*)(sm + SM_CNT);

    int tid = threadIdx.x, lane = tid & 31, wid = tid >> 5;
    int c0  = blockIdx.x * 8;

    for (int i = tid; i < NTOT; i += 256) ids_s[i] = (unsigned short)ids[i];
    __syncthreads();

    // per-window ordered packed lists: H first then O, (j<<11)|n
    for (int w = tid; w < NWIN; w += 256) {
        int hc = 0;
        for (int j = 0; j < 32; j++) {
            int n = ids_s[w * 32 + j];
            if (n < NH) uord[w * 32 + hc++] = (unsigned short)((j << 11) | n);
        }
        cnt_s[w] = hc;
        int oc = hc;
        for (int j = 0; j < 32; j++) {
            int n = ids_s[w * 32 + j];
            if (n >= NH) uord[w * 32 + oc++] = (unsigned short)((j << 11) | n);
        }
    }
    // position of each unit per sweep
    for (int p = tid; p < NTOT; p += 256) {
        int n = ids_s[p];
        upos[n + (p >= 1536 ? 1536 : 0)] = (unsigned short)p;
    }
    // state floats s_s[n*8+c]
    for (int i = tid; i < 1536; i += 256) {
#pragma unroll
        for (int c = 0; c < 8; c++) {
            float v = (i < NH) ? s1i[(size_t)(c0 + c) * NH + i]
                               : s2i[(size_t)(c0 + c) * NOUT + (i - NH)];
            s_s[i * 8 + c] = (v > 0.5f) ? 1.f : 0.f;
        }
    }

    // register gaps
    ull rH[4][4], rO[2][4];
#pragma unroll
    for (int u = 0; u < 4; u++)
#pragma unroll
        for (int p = 0; p < 4; p++)
            rH[u][p] = pack2f(g_gapH[(size_t)(c0 + 2 * p) * NH + 4 * tid + u],
                              g_gapH[(size_t)(c0 + 2 * p + 1) * NH + 4 * tid + u]);
#pragma unroll
    for (int v = 0; v < 2; v++)
#pragma unroll
        for (int p = 0; p < 4; p++)
            rO[v][p] = pack2f(g_gapO[(size_t)(c0 + 2 * p) * NOUT + 2 * tid + v],
                              g_gapO[(size_t)(c0 + 2 * p + 1) * NOUT + 2 * tid + v]);
    __syncthreads();

    // my 12 owned positions
    int mypos[12];
#pragma unroll
    for (int k = 0; k < 4; k++) {
        mypos[k]     = upos[4 * tid + k];
        mypos[k + 4] = upos[4 * tid + k + 1536];
    }
#pragma unroll
    for (int k = 0; k < 2; k++) {
        mypos[8 + k]  = upos[NH + 2 * tid + k];
        mypos[10 + k] = upos[NH + 2 * tid + k + 1536];
    }

#define STAGE_WIN(NBASE)                                                     \
    {                                                                        \
        _Pragma("unroll")                                                    \
        for (int k = 0; k < 12; k++) {                                       \
            int pos = mypos[k];                                              \
            if (pos >= (NBASE) && pos < (NBASE) + 32) {                      \
                int j = pos - (NBASE);                                       \
                ull* bq = (ull*)bg_s + j * 4;                                \
                if (k < 8) {                                                 \
                    int u = k & 3;                                           \
                    _Pragma("unroll")                                        \
                    for (int p = 0; p < 4; p++) bq[p] = rH[u][p];            \
                } else {                                                     \
                    int v = k & 1;                                           \
                    _Pragma("unroll")                                        \
                    for (int p = 0; p < 4; p++) bq[p] = rO[v][p];            \
                }                                                            \
            }                                                                \
        }                                                                    \
    }

    // ---- pre-loop staging for window 0 ----
    STAGE_WIN(0)
    ((float4*)cw_s)[tid] = ((const float4*)g_CW)[tid];
    if (tid < 64) {
        int j = tid >> 1, h = tid & 1;
        *(float4*)&th_st[j * 8 + 4 * h] =
            *(const float4*)&g_TH[(size_t)j * B_ + c0 + 4 * h];
    }
#pragma unroll
    for (int kk = 0; kk < 4; kk++) {
        int v = uord[wid * 4 + kk];
        int n = v & 0x7FF;
        const float* rp; int nl;
        if (n < NH) { rp = g_W2T + (size_t)n * NOUT; nl = 16; }
        else        { rp = W2 + (size_t)(n - NH) * NH; nl = 32; }
        if (lane < nl)
            asm volatile("prefetch.global.L1 [%0];" :: "l"(rp + lane * 32));
    }
    __syncthreads();

    for (int w = 0; w < NWIN; w++) {
        int base = w * 32;

        // ===== sequencer: warp c = chain c, lane j = update j (push model) =====
        {
            int c = wid;
            int n = ids_s[base + lane];
            float g   = bg_s[lane * 8 + c];
            float th  = th_st[lane * 8 + c];
            float ov  = s_s[n * 8 + c];
            float myd = 0.f;
            const float* cwp = cw_s + lane;
#pragma unroll
            for (int j = 0; j < 32; j++) {
                if (lane == j) {
                    float nv = (g > th) ? 1.f : 0.f;
                    myd = nv - ov;
                }
                float d = __shfl_sync(0xffffffffu, myd, j);
                g = fmaf(d, cwp[j * 32], g);   // cw==0 for same-layer / i>=j
            }
            d_s[lane * 8 + c] = myd;
            s_s[n * 8 + c] = ov + myd;
        }
        __syncthreads();

        // ===== apply phase =====
        int hcnt = cnt_s[w];
        for (int k = 0; k < hcnt; k++) {
            int v = uord[base + k];
            int n = v & 0x7FF, j = v >> 11;
            float2 wv = __ldg((const float2*)(g_W2T + (size_t)n * NOUT + 2 * tid));
            ull w0 = pack2f(wv.x, wv.x);
            ull w1 = pack2f(wv.y, wv.y);
            const ull* dp = (const ull*)(d_s + j * 8);
#pragma unroll
            for (int p = 0; p < 4; p++) {
                ull d = dp[p];
                fma2(rO[0][p], d, w0);
                fma2(rO[1][p], d, w1);
            }
        }
        for (int k = hcnt; k < 32; k++) {
            int v = uord[base + k];
            int o = (v & 0x7FF) - NH, j = v >> 11;
            float4 wv = __ldg((const float4*)(W2 + (size_t)o * NH + 4 * tid));
            ull w0 = pack2f(wv.x, wv.x);
            ull w1 = pack2f(wv.y, wv.y);
            ull w2_ = pack2f(wv.z, wv.z);
            ull w3 = pack2f(wv.w, wv.w);
            const ull* dp = (const ull*)(d_s + j * 8);
#pragma unroll
            for (int p = 0; p < 4; p++) {
                ull d = dp[p];
                fma2(rH[0][p], d, w0);
                fma2(rH[1][p], d, w1);
                fma2(rH[2][p], d, w2_);
                fma2(rH[3][p], d, w3);
            }
        }

        // ===== stage/prefetch for next window =====
        if (w + 1 < NWIN) {
            int nb = base + 32;
            STAGE_WIN(nb)
            ((float4*)cw_s)[tid] =
                ((const float4*)(g_CW + (size_t)(w + 1) * 1024))[tid];
            if (tid < 64) {
                int j = tid >> 1, h = tid & 1;
                *(float4*)&th_st[j * 8 + 4 * h] =
                    *(const float4*)&g_TH[(size_t)(nb + j) * B_ + c0 + 4 * h];
            }
#pragma unroll
            for (int kk = 0; kk < 4; kk++) {
                int v = uord[nb + wid * 4 + kk];
                int n = v & 0x7FF;
                const float* rp; int nl;
                if (n < NH) { rp = g_W2T + (size_t)n * NOUT; nl = 16; }
                else        { rp = W2 + (size_t)(n - NH) * NH; nl = 32; }
                if (lane < nl)
                    asm volatile("prefetch.global.L1 [%0];" :: "l"(rp + lane * 32));
            }
        }
        __syncthreads();
    }

    // ===== epilogue =====
#pragma unroll
    for (int c = 0; c < 8; c++) {
        int b = c0 + c;
        size_t rb4 = (size_t)b * 640;
        ((float4*)out)[rb4 + tid] = ((const float4*)x)[(size_t)b * 256 + tid];
        float4 v1;
        v1.x = s_s[(4 * tid + 0) * 8 + c];
        v1.y = s_s[(4 * tid + 1) * 8 + c];
        v1.z = s_s[(4 * tid + 2) * 8 + c];
        v1.w = s_s[(4 * tid + 3) * 8 + c];
        ((float4*)out)[rb4 + 256 + tid] = v1;
        if (tid < 128) {
            float4 v2;
            v2.x = s_s[(1024 + 4 * tid + 0) * 8 + c];
            v2.y = s_s[(1024 + 4 * tid + 1) * 8 + c];
            v2.z = s_s[(1024 + 4 * tid + 2) * 8 + c];
            v2.w = s_s[(1024 + 4 * tid + 3) * 8 + c];
            ((float4*)out)[rb4 + 512 + tid] = v2;
        }
    }
}

// ---------------------------------------------------------------------------
extern "C" void kernel_launch(void* const* d_in, const int* in_sizes, int n_in,
                              void* d_out, int out_size)
{
    const float* x   = (const float*)d_in[0];
    const float* s1i = (const float*)d_in[1];
    const float* s2i = (const float*)d_in[2];
    const float* W1  = (const float*)d_in[3];
    const float* b1  = (const float*)d_in[4];
    const float* W2  = (const float*)d_in[5];
    const float* b2  = (const float*)d_in[6];
    const float* u   = (const float*)d_in[7];
    const int*   ids = (const int*)d_in[8];
    float* out = (float*)d_out;

    float *pA, *pWH, *pW2T, *pGH, *pGO;
    cudaGetSymbolAddress((void**)&pA,   g_A);
    cudaGetSymbolAddress((void**)&pWH,  g_WH);
    cudaGetSymbolAddress((void**)&pW2T, g_W2T);
    cudaGetSymbolAddress((void**)&pGH,  g_gapH);
    cudaGetSymbolAddress((void**)&pGO,  g_gapO);

    prep_k     <<<30080, 256>>>(x, s2i, W1, W2, u, ids);
    gemm_bias_k<<<dim3(16, 16), 256>>>(pA,  pWH,  b1, pGH, 2048, 1024, 1536);
    gemm_bias_k<<<dim3(8, 16),  256>>>(s1i, pW2T, b2, pGO, 2048, 512, 1024);

    cudaFuncSetAttribute(gibbs_k, cudaFuncAttributeMaxDynamicSharedMemorySize,
                         SMEM_BYTES);
    gibbs_k<<<256, 256, SMEM_BYTES>>>(x, s1i, s2i, W2, ids, out);
}